// round 7
// baseline (speedup 1.0000x reference)
#include <cuda_runtime.h>
#include <cstdint>

// YOLOv1 loss: [B,7,7,30] x2 f32 -> scalar. HBM-bound (~193 MB read).
// R7: warp-autonomous double-buffered pipelines (as R6), but:
//   - CW=32: all lanes compute (was 16) -> compute warp-ops per cell halved
//   - LDS.64 (float2) smem reads, conflict-free -> LDS ops halved
//   - 2 warps/block, 30.7 KB static smem -> 7 blocks/SM = 14 warps
// Goal: cut issued ops per byte ~2x so issue slots go to feeding DRAM.

#define TPB    64
#define NWARP  (TPB / 32)
#define DIM    30
#define CW     32                 // cells per warp-tile (one per lane)
#define WFL    (CW * DIM)         // 960 floats per tensor per warp-tile
#define NV4W   (WFL / 4)          // 240 float4
#define EPSF   1e-6f
#define MAX_BLOCKS 4096

__device__ float g_part[MAX_BLOCKS];
__device__ unsigned int g_count = 0;

__device__ __forceinline__ float sq(float x) { return x * x; }

__device__ __forceinline__ void cp16(uint32_t smem_dst, const void* gsrc) {
    asm volatile("cp.async.cg.shared.global [%0], [%1], 16;\n"
                 :: "r"(smem_dst), "l"(gsrc));
}
__device__ __forceinline__ void cp4(uint32_t smem_dst, const void* gsrc) {
    asm volatile("cp.async.ca.shared.global [%0], [%1], 4;\n"
                 :: "r"(smem_dst), "l"(gsrc));
}

__device__ __forceinline__ float iou5(float tx, float ty, float tw, float th,
                                      float px, float py, float pw, float ph) {
    float ax1 = tx - 0.5f * tw, ax2 = tx + 0.5f * tw;
    float ay1 = ty - 0.5f * th, ay2 = ty + 0.5f * th;
    float bx1 = px - 0.5f * pw, bx2 = px + 0.5f * pw;
    float by1 = py - 0.5f * ph, by2 = py + 0.5f * ph;
    float iw = fmaxf(fminf(ax2, bx2) - fmaxf(ax1, bx1), 0.0f);
    float ih = fmaxf(fminf(ay2, by2) - fmaxf(ay1, by1), 0.0f);
    float inter = iw * ih;
    float a1 = fabsf((ax2 - ax1) * (ay2 - ay1));
    float a2 = fabsf((bx2 - bx1) * (by2 - by1));
    return inter / (a1 + a2 - inter + EPSF);
}

__global__ void __launch_bounds__(TPB, 7)
yolo_loss_kernel(const float* __restrict__ yt_g,
                 const float* __restrict__ yp_g,
                 long long n_cells,
                 long long n_wtiles,
                 float* __restrict__ out,
                 double inv_batch) {
    // [warp][stage][tensor][floats]
    __shared__ float sbuf[NWARP][2][2][WFL];   // 30720 B
    __shared__ float wsum[NWARP];
    __shared__ int   s_last;

    const int tid  = threadIdx.x;
    const int wid  = tid >> 5;
    const int lane = tid & 31;

    const long long wstride = (long long)gridDim.x * NWARP;
    long long wt = (long long)blockIdx.x * NWARP + wid;

    const uint32_t s0 =
        (uint32_t)__cvta_generic_to_shared(&sbuf[wid][0][0][0]);

    // Issue one warp-tile into stage `buf` (one commit group per call).
    auto issue = [&](long long w, int buf) {
        long long cbase = w * CW;
        uint32_t st_b = s0 + (uint32_t)(buf * 2 + 0) * (WFL * 4u);
        uint32_t sp_b = s0 + (uint32_t)(buf * 2 + 1) * (WFL * 4u);
        const float* yt = yt_g + cbase * DIM;
        const float* yp = yp_g + cbase * DIM;
        if (cbase + CW <= n_cells) {
            const float4* yt4 = (const float4*)yt;
            const float4* yp4 = (const float4*)yp;
#pragma unroll
            for (int k = 0; k < 8; k++) {          // 240 float4 / 32 lanes
                int j = k * 32 + lane;
                if (j < NV4W) {
                    cp16(st_b + j * 16, yt4 + j);
                    cp16(sp_b + j * 16, yp4 + j);
                }
            }
        } else {
            int nflt = (int)(n_cells - cbase) * DIM;
            for (int j = lane; j < nflt; j += 32) {
                cp4(st_b + j * 4, yt + j);
                cp4(sp_b + j * 4, yp + j);
            }
        }
        asm volatile("cp.async.commit_group;\n" ::: "memory");
    };

    float acc = 0.0f;
    int buf = 0;

    if (wt < n_wtiles) issue(wt, 0);

    for (; wt < n_wtiles; wt += wstride) {
        long long nxt = wt + wstride;
        bool has_next = (nxt < n_wtiles);
        if (has_next) issue(nxt, buf ^ 1);

        if (has_next) asm volatile("cp.async.wait_group 1;\n" ::: "memory");
        else          asm volatile("cp.async.wait_group 0;\n" ::: "memory");
        __syncwarp();

        long long cbase = wt * CW;
        if (cbase + lane < n_cells) {
            // float2 reads: cell base = lane*120 B (8B aligned), conflict-free.
            const float2* t2 = (const float2*)&sbuf[wid][buf][0][lane * DIM];
            const float2* p2 = (const float2*)&sbuf[wid][buf][1][lane * DIM];

            float2 ta = t2[0], tb = t2[1], tc = t2[2];
            float2 pa = p2[0], pb = p2[1], pc = p2[2], pd = p2[3], pe = p2[4];
            float t0 = ta.x, t1 = ta.y, t2v = tb.x, t3 = tb.y, t4v = tc.x;
            float p0 = pa.x, p1 = pa.y, pw2 = pb.x, p3 = pb.y, p4 = pc.x;
            float p5 = pc.y, p6 = pd.x, p7 = pd.y, p8 = pe.x, p9 = pe.y;

            float obj = (t4v == 1.0f) ? 1.0f : 0.0f;

            float iou1 = iou5(t0, t1, t2v, t3, p0, p1, pw2, p3);
            float iou2 = iou5(t0, t1, t2v, t3, p5, p6, p7, p8);
            bool best1 = iou1 > iou2;

            float bx = best1 ? p0 : p5, by = best1 ? p1 : p6;
            float bw = best1 ? pw2 : p7, bh = best1 ? p3 : p8;
            float ch = best1 ? p4 : p9, oh = best1 ? p9 : p4;

            float xy = sq(t0 - bx) + sq(t1 - by);
            float wh = sq(sqrtf(t2v) - sqrtf(fabsf(bw + EPSF)))
                     + sq(sqrtf(t3) - sqrtf(fabsf(bh + EPSF)));
            float obj_conf = sq(t4v - ch);
            float noio = 0.5f * oh * oh;
            float noc  = 0.5f * (sq(t4v - p4) + sq(t4v - p9));

            float cls = 0.0f;
#pragma unroll
            for (int k = 5; k < 15; k++) {      // floats 10..29 as float2
                float2 tv = t2[k];
                float2 pv = p2[k];
                cls += sq(tv.x - pv.x) + sq(tv.y - pv.y);
            }

            acc += obj * (5.0f * (xy + wh) + obj_conf + noio + cls)
                 + (1.0f - obj) * noc;
        }

        __syncwarp();   // all lanes done reading buf before it is refilled
        buf ^= 1;
    }

    // Warp reduce, then block reduce (once).
#pragma unroll
    for (int o = 16; o > 0; o >>= 1)
        acc += __shfl_xor_sync(0xFFFFFFFFu, acc, o);

    if (lane == 0) wsum[wid] = acc;
    __syncthreads();

    if (tid == 0) {
        float s = 0.0f;
#pragma unroll
        for (int i = 0; i < NWARP; i++) s += wsum[i];
        g_part[blockIdx.x] = s;
        __threadfence();
        unsigned int prev = atomicAdd(&g_count, 1u);
        s_last = (prev == gridDim.x - 1) ? 1 : 0;
    }
    __syncthreads();

    if (s_last) {
        int nb = gridDim.x;
        const volatile float* vp = g_part;
        double s = 0.0;
        for (int i = tid; i < nb; i += TPB)
            s += (double)vp[i];
#pragma unroll
        for (int o = 16; o > 0; o >>= 1)
            s += __shfl_xor_sync(0xFFFFFFFFu, s, o);

        __shared__ double dsum[NWARP];
        if (lane == 0) dsum[wid] = s;
        __syncthreads();

        if (tid == 0) {
            double tot = 0.0;
#pragma unroll
            for (int i = 0; i < NWARP; i++) tot += dsum[i];
            out[0] = (float)(tot * inv_batch);
            g_count = 0;   // reset for next graph replay
        }
    }
}

extern "C" void kernel_launch(void* const* d_in, const int* in_sizes, int n_in,
                              void* d_out, int out_size) {
    const float* yt = (const float*)d_in[0];   // y_trues
    const float* yp = (const float*)d_in[1];   // y_preds
    long long n_cells  = (long long)in_sizes[0] / DIM;    // batch * 49
    long long batch    = n_cells / 49;
    long long n_wtiles = (n_cells + CW - 1) / CW;

    // Persistent-ish grid: ~7 blocks/SM on 148-152 SMs.
    int blocks = 1036;
    long long need = (n_wtiles + NWARP - 1) / NWARP;
    if ((long long)blocks > need) blocks = (int)need;
    if (blocks > MAX_BLOCKS) blocks = MAX_BLOCKS;

    yolo_loss_kernel<<<blocks, TPB>>>(yt, yp, n_cells, n_wtiles,
                                      (float*)d_out, 1.0 / (double)batch);
}